// round 15
// baseline (speedup 1.0000x reference)
#include <cuda_runtime.h>

#define BATCH   8
#define NPTS    4096
#define THREADS 128
#define PTS     8                        // x points per thread (4 packed pairs)
#define NPAIR   (PTS / 2)
#define PTS_BLK (THREADS * PTS)          // 1024 x-points per tile
#define XT      (NPTS / PTS_BLK)         // 4 x tiles
#define NC      32                       // y chunks
#define CH      (NPTS / NC)              // 128 y-points per chunk
#define PH      (CH / 32)                // 4 column-reduce phases
#define NCTAS   (BATCH * XT * NC)        // 1024
#define CPITCH  132                      // transposed col pitch (conflict-free)

// Scratch (allocation-free contract). Zero-init == "empty" keys; each replay
// resets everything it consumed -> graph-replay deterministic.
__device__ unsigned           g_xkey[BATCH * NPTS];
__device__ unsigned           g_ykey[BATCH * NPTS];
__device__ int                g_xctr[BATCH * XT];
__device__ int                g_yctr[BATCH * NC];
__device__ unsigned long long g_total = 0ull;
__device__ int                g_done  = 0;

// ---- packed f32x2 helpers -------------------------------------------------
__device__ __forceinline__ unsigned long long fma2(unsigned long long a,
                                                   unsigned long long b,
                                                   unsigned long long c) {
    unsigned long long d;
    asm("fma.rn.f32x2 %0, %1, %2, %3;" : "=l"(d) : "l"(a), "l"(b), "l"(c));
    return d;
}
__device__ __forceinline__ unsigned long long add2(unsigned long long a,
                                                   unsigned long long b) {
    unsigned long long d;
    asm("add.rn.f32x2 %0, %1, %2;" : "=l"(d) : "l"(a), "l"(b));
    return d;
}
__device__ __forceinline__ unsigned long long pack2(float lo, float hi) {
    unsigned long long v;
    asm("mov.b64 %0, {%1, %2};" : "=l"(v) : "f"(lo), "f"(hi));
    return v;
}
__device__ __forceinline__ float2 unpack2(unsigned long long v) {
    float2 r;
    asm("mov.b64 {%0, %1}, %2;" : "=f"(r.x), "=f"(r.y) : "l"(v));
    return r;
}

// Order-preserving float -> uint map, inverted: min(f) == max(key), key 0 = empty.
__device__ __forceinline__ unsigned min_key(float f) {
    unsigned u = __float_as_uint(f);
    u ^= (unsigned)(((int)u >> 31)) | 0x80000000u;
    return ~u;
}
__device__ __forceinline__ float key_to_float(unsigned key) {
    unsigned mono = ~key;
    unsigned bits = (mono & 0x80000000u) ? (mono ^ 0x80000000u) : ~mono;
    return __uint_as_float(bits);
}

// Ordering rides on atomics (no membar -> no CCTL.IVALL L1 flush).
__device__ __forceinline__ int atom_add_acq_rel(int* p, int v) {
    int old;
    asm volatile("atom.acq_rel.gpu.global.add.s32 %0, [%1], %2;"
                 : "=r"(old) : "l"(p), "r"(v) : "memory");
    return old;
}
__device__ __forceinline__ void red_add_release(unsigned long long* p,
                                                unsigned long long v) {
    asm volatile("red.release.gpu.global.add.u64 [%0], %1;"
                 :: "l"(p), "l"(v) : "memory");
}

// ---- single symmetric fused kernel ----------------------------------------
// Each CTA: one (b, x-tile[1024], y-chunk[128]) tile. Distances computed ONCE,
// folded into BOTH x-side row mins and y-side column mins via atomicMax keys.
// Column mins are reduced in 4 phases of 32 columns to bound smem.
__global__ void __launch_bounds__(THREADS, 7)
chamfer_fused(const float* __restrict__ X, const float* __restrict__ Y,
              float* __restrict__ out) {
    __shared__ float4 sq[CH * 2];           // (q,q,q1,q1 | q2,q2,qq,qq)
    __shared__ float  scol[32 * CPITCH];    // transposed: scol[jj][t2]
    __shared__ float  red[THREADS];
    __shared__ int    sflags;

    int bid = blockIdx.x;
    int c   = bid & (NC - 1);  bid >>= 5;
    int xt  = bid & (XT - 1);  bid >>= 2;
    int b   = bid;

    const float* Xb = X + b * 3 * NPTS;
    const float* Yb = Y + b * 3 * NPTS;
    int tid = threadIdx.x;

    // Stage y chunk: one point per thread (duplicated lanes for f32x2).
    {
        int gm   = c * CH + tid;
        float q0 = Yb[gm];
        float q1 = Yb[gm + NPTS];
        float q2 = Yb[gm + 2 * NPTS];
        float qq = q0*q0 + q1*q1 + q2*q2;
        sq[tid * 2 + 0] = make_float4(q0, q0, q1, q1);
        sq[tid * 2 + 1] = make_float4(q2, q2, qq, qq);
    }

    // 4 packed x pairs per thread: coeffs -2x, plus packed |x|^2.
    unsigned long long pa0[NPAIR], pa1[NPAIR], pa2[NPAIR], pp[NPAIR];
    float mn[PTS];
    #pragma unroll
    for (int p = 0; p < NPAIR; p++) {
        int n0 = xt * PTS_BLK + (2*p)   * THREADS + tid;
        int n1 = xt * PTS_BLK + (2*p+1) * THREADS + tid;
        float x0l = Xb[n0],          x0h = Xb[n1];
        float x1l = Xb[n0 + NPTS],   x1h = Xb[n1 + NPTS];
        float x2l = Xb[n0 + 2*NPTS], x2h = Xb[n1 + 2*NPTS];
        pa0[p] = pack2(-2.0f * x0l, -2.0f * x0h);
        pa1[p] = pack2(-2.0f * x1l, -2.0f * x1h);
        pa2[p] = pack2(-2.0f * x2l, -2.0f * x2h);
        pp[p]  = pack2(x0l*x0l + x1l*x1l + x2l*x2l,
                       x0h*x0h + x1h*x1h + x2h*x2h);
        mn[2*p] = 3.0e38f; mn[2*p+1] = 3.0e38f;
    }
    __syncthreads();

    // Main loop in 4 phases of 32 y-points each.
    const ulonglong2* s2 = reinterpret_cast<const ulonglong2*>(sq);
    #pragma unroll 1
    for (int ph = 0; ph < PH; ph++) {
        // t = qq - 2 x.q  (row mins use t; col mins use t + pp = d).
        #pragma unroll 8
        for (int jj = 0; jj < 32; jj++) {
            int j = ph * 32 + jj;
            ulonglong2 A = s2[2*j];           // {q0,q0} {q1,q1}
            ulonglong2 B = s2[2*j + 1];       // {q2,q2} {qq,qq}
            float cv[NPAIR];
            #pragma unroll
            for (int p = 0; p < NPAIR; p++) {
                unsigned long long t =
                    fma2(pa0[p], A.x, fma2(pa1[p], A.y, fma2(pa2[p], B.x, B.y)));
                float2 tf = unpack2(t);
                mn[2*p]   = fminf(mn[2*p],   tf.x);
                mn[2*p+1] = fminf(mn[2*p+1], tf.y);
                float2 cf = unpack2(add2(t, pp[p]));
                cv[p] = fminf(cf.x, cf.y);
            }
            scol[jj * CPITCH + tid] =
                fminf(fminf(cv[0], cv[1]), fminf(cv[2], cv[3]));
        }
        __syncthreads();

        // Cross-thread column mins for this phase's 32 columns:
        // 4 threads per column, conflict-free (bank == (tid + 4i) % 32).
        {
            int col = tid >> 2;               // 0..31
            int sub = tid & 3;
            float v = 3.0e38f;
            #pragma unroll 8
            for (int i = 0; i < THREADS / 4; i++)
                v = fminf(v, scol[col * CPITCH + i * 4 + sub]);
            v = fminf(v, __shfl_xor_sync(0xffffffffu, v, 1));
            v = fminf(v, __shfl_xor_sync(0xffffffffu, v, 2));
            if (sub == 0)
                atomicMax(&g_ykey[b * NPTS + c * CH + ph * 32 + col],
                          min_key(v));
        }
        __syncthreads();
    }

    // Fold x-side row mins (fire-and-forget REDG.MAX).
    unsigned* gx = g_xkey + b * NPTS + xt * PTS_BLK;
    #pragma unroll
    for (int k = 0; k < PTS; k++)
        atomicMax(&gx[k * THREADS + tid], min_key(mn[k]));

    // ---- tile-last epilogues (ordering via acq_rel atomics, no membar) ----
    if (tid == 0) {
        int f = 0;
        if (atom_add_acq_rel(&g_xctr[b * XT + xt], 1) == NC - 1) f |= 1;
        if (atom_add_acq_rel(&g_yctr[b * NC + c], 1) == XT - 1) f |= 2;
        sflags = f;
    }
    __syncthreads();
    int f = sflags;

    if (f) {
        float part = 0.0f;
        if (f & 1) {                       // x-tile complete: its 1024 points
            if (tid == 0) g_xctr[b * XT + xt] = 0;
            #pragma unroll
            for (int p = 0; p < NPAIR; p++) {
                float2 pf = unpack2(pp[p]);
                int i0 = (2*p)   * THREADS + tid;
                int i1 = (2*p+1) * THREADS + tid;
                unsigned k0 = *((volatile unsigned*)&gx[i0]);
                unsigned k1 = *((volatile unsigned*)&gx[i1]);
                gx[i0] = 0u; gx[i1] = 0u;  // reset for next replay
                part += key_to_float(k0) + pf.x;
                part += key_to_float(k1) + pf.y;
            }
        }
        if (f & 2) {                       // y-chunk complete: 128 full dists
            if (tid == 0) g_yctr[b * NC + c] = 0;
            unsigned* gy = g_ykey + b * NPTS + c * CH + tid;
            unsigned k = *((volatile unsigned*)gy);
            *gy = 0u;                      // reset for next replay
            part += key_to_float(k);
        }
        red[tid] = part;
        __syncthreads();
        #pragma unroll
        for (int st = THREADS / 2; st > 0; st >>= 1) {
            if (tid < st) red[tid] += red[tid + st];
            __syncthreads();
        }
        if (tid == 0)                      // deterministic fixed-point fold
            red_add_release(&g_total,
                (unsigned long long)((double)red[0] * 4294967296.0));
    }

    if (tid == 0) {
        if (atom_add_acq_rel(&g_done, 1) == NCTAS - 1) {
            unsigned long long tot = *((volatile unsigned long long*)&g_total);
            out[0] = (float)((double)tot * (1.0 / 4294967296.0)
                             / (double)(NPTS * BATCH));
            g_total = 0ull;                // reset for next replay
            g_done  = 0;
        }
    }
}

extern "C" void kernel_launch(void* const* d_in, const int* in_sizes, int n_in,
                              void* d_out, int out_size) {
    const float* x = (const float*)d_in[0];
    const float* y = (const float*)d_in[1];
    float* out = (float*)d_out;

    chamfer_fused<<<NCTAS, THREADS>>>(x, y, out);
}

// round 16
// speedup vs baseline: 1.1071x; 1.1071x over previous
#include <cuda_runtime.h>

#define BATCH   8
#define NPTS    4096
#define THREADS 128
#define PTS     8                        // x points per thread (4 packed pairs)
#define NPAIR   (PTS / 2)
#define PTS_BLK (THREADS * PTS)          // 1024 x-points per tile
#define XT      (NPTS / PTS_BLK)         // 4 x tiles
#define NC      64                       // y chunks
#define CH      (NPTS / NC)              // 64 y-points per chunk
#define PH      (CH / 32)                // 2 column-reduce phases
#define NCTAS   (BATCH * XT * NC)        // 2048
#define CPITCH  132                      // transposed col pitch (conflict-free)

// Scratch (allocation-free contract). Zero-init == "empty" keys; each replay
// resets everything it consumed -> graph-replay deterministic.
__device__ unsigned           g_xkey[BATCH * NPTS];
__device__ unsigned           g_ykey[BATCH * NPTS];
__device__ int                g_xctr[BATCH * XT];
__device__ int                g_yctr[BATCH * NC];
__device__ unsigned long long g_total = 0ull;
__device__ int                g_done  = 0;

// ---- packed f32x2 helpers -------------------------------------------------
__device__ __forceinline__ unsigned long long fma2(unsigned long long a,
                                                   unsigned long long b,
                                                   unsigned long long c) {
    unsigned long long d;
    asm("fma.rn.f32x2 %0, %1, %2, %3;" : "=l"(d) : "l"(a), "l"(b), "l"(c));
    return d;
}
__device__ __forceinline__ unsigned long long add2(unsigned long long a,
                                                   unsigned long long b) {
    unsigned long long d;
    asm("add.rn.f32x2 %0, %1, %2;" : "=l"(d) : "l"(a), "l"(b));
    return d;
}
__device__ __forceinline__ unsigned long long pack2(float lo, float hi) {
    unsigned long long v;
    asm("mov.b64 %0, {%1, %2};" : "=l"(v) : "f"(lo), "f"(hi));
    return v;
}
__device__ __forceinline__ float2 unpack2(unsigned long long v) {
    float2 r;
    asm("mov.b64 {%0, %1}, %2;" : "=f"(r.x), "=f"(r.y) : "l"(v));
    return r;
}

// Order-preserving float -> uint map, inverted: min(f) == max(key), key 0 = empty.
__device__ __forceinline__ unsigned min_key(float f) {
    unsigned u = __float_as_uint(f);
    u ^= (unsigned)(((int)u >> 31)) | 0x80000000u;
    return ~u;
}
__device__ __forceinline__ float key_to_float(unsigned key) {
    unsigned mono = ~key;
    unsigned bits = (mono & 0x80000000u) ? (mono ^ 0x80000000u) : ~mono;
    return __uint_as_float(bits);
}

// Ordering rides on atomics (no membar -> no CCTL.IVALL L1 flush).
__device__ __forceinline__ int atom_add_acq_rel(int* p, int v) {
    int old;
    asm volatile("atom.acq_rel.gpu.global.add.s32 %0, [%1], %2;"
                 : "=r"(old) : "l"(p), "r"(v) : "memory");
    return old;
}
__device__ __forceinline__ void red_add_release(unsigned long long* p,
                                                unsigned long long v) {
    asm volatile("red.release.gpu.global.add.u64 [%0], %1;"
                 :: "l"(p), "l"(v) : "memory");
}

// ---- single symmetric fused kernel ----------------------------------------
// Each CTA: one (b, x-tile[1024], y-chunk[64]) tile. Full squared distance
// d = |x|^2 + |y|^2 - 2 x.y computed ONCE per pair (|x|^2 folded into the
// fma-chain seed), folded into BOTH x-side row mins and y-side column mins.
__global__ void __launch_bounds__(THREADS, 7)
chamfer_fused(const float* __restrict__ X, const float* __restrict__ Y,
              float* __restrict__ out) {
    __shared__ float4 sq[CH * 2];           // (q,q,q1,q1 | q2,q2,qq,qq)
    __shared__ float  scol[32 * CPITCH];    // transposed: scol[jj][t2]
    __shared__ float  red[THREADS];
    __shared__ int    sflags;

    int bid = blockIdx.x;
    int c   = bid & (NC - 1);  bid >>= 6;
    int xt  = bid & (XT - 1);  bid >>= 2;
    int b   = bid;

    const float* Xb = X + b * 3 * NPTS;
    const float* Yb = Y + b * 3 * NPTS;
    int tid = threadIdx.x;

    // Stage y chunk (duplicated lanes for f32x2 broadcast).
    if (tid < CH) {
        int gm   = c * CH + tid;
        float q0 = Yb[gm];
        float q1 = Yb[gm + NPTS];
        float q2 = Yb[gm + 2 * NPTS];
        float qq = q0*q0 + q1*q1 + q2*q2;
        sq[tid * 2 + 0] = make_float4(q0, q0, q1, q1);
        sq[tid * 2 + 1] = make_float4(q2, q2, qq, qq);
    }

    // 4 packed x pairs per thread: coeffs -2x, plus packed |x|^2.
    unsigned long long pa0[NPAIR], pa1[NPAIR], pa2[NPAIR], pp[NPAIR];
    float mn[PTS];
    #pragma unroll
    for (int p = 0; p < NPAIR; p++) {
        int n0 = xt * PTS_BLK + (2*p)   * THREADS + tid;
        int n1 = xt * PTS_BLK + (2*p+1) * THREADS + tid;
        float x0l = Xb[n0],          x0h = Xb[n1];
        float x1l = Xb[n0 + NPTS],   x1h = Xb[n1 + NPTS];
        float x2l = Xb[n0 + 2*NPTS], x2h = Xb[n1 + 2*NPTS];
        pa0[p] = pack2(-2.0f * x0l, -2.0f * x0h);
        pa1[p] = pack2(-2.0f * x1l, -2.0f * x1h);
        pa2[p] = pack2(-2.0f * x2l, -2.0f * x2h);
        pp[p]  = pack2(x0l*x0l + x1l*x1l + x2l*x2l,
                       x0h*x0h + x1h*x1h + x2h*x2h);
        mn[2*p] = 3.0e38f; mn[2*p+1] = 3.0e38f;
    }
    __syncthreads();

    // Main loop in PH phases of 32 y-points each. One value stream: the true
    // squared distance d; only 4 unpacks per j-iter.
    const ulonglong2* s2 = reinterpret_cast<const ulonglong2*>(sq);
    #pragma unroll 1
    for (int ph = 0; ph < PH; ph++) {
        #pragma unroll 8
        for (int jj = 0; jj < 32; jj++) {
            int j = ph * 32 + jj;
            ulonglong2 A = s2[2*j];           // {q0,q0} {q1,q1}
            ulonglong2 B = s2[2*j + 1];       // {q2,q2} {qq,qq}
            float cv[NPAIR];
            #pragma unroll
            for (int p = 0; p < NPAIR; p++) {
                unsigned long long d =
                    fma2(pa0[p], A.x,
                         fma2(pa1[p], A.y,
                              fma2(pa2[p], B.x, add2(B.y, pp[p]))));
                float2 df = unpack2(d);
                mn[2*p]   = fminf(mn[2*p],   df.x);
                mn[2*p+1] = fminf(mn[2*p+1], df.y);
                cv[p] = fminf(df.x, df.y);
            }
            scol[jj * CPITCH + tid] =
                fminf(fminf(cv[0], cv[1]), fminf(cv[2], cv[3]));
        }
        __syncthreads();

        // Cross-thread column mins for this phase's 32 columns:
        // 4 threads per column, conflict-free (bank == (tid + 4i) % 32).
        {
            int col = tid >> 2;               // 0..31
            int sub = tid & 3;
            float v = 3.0e38f;
            #pragma unroll 8
            for (int i = 0; i < THREADS / 4; i++)
                v = fminf(v, scol[col * CPITCH + i * 4 + sub]);
            v = fminf(v, __shfl_xor_sync(0xffffffffu, v, 1));
            v = fminf(v, __shfl_xor_sync(0xffffffffu, v, 2));
            if (sub == 0)
                atomicMax(&g_ykey[b * NPTS + c * CH + ph * 32 + col],
                          min_key(v));
        }
        __syncthreads();
    }

    // Fold x-side row mins (true distances; fire-and-forget REDG.MAX).
    unsigned* gx = g_xkey + b * NPTS + xt * PTS_BLK;
    #pragma unroll
    for (int k = 0; k < PTS; k++)
        atomicMax(&gx[k * THREADS + tid], min_key(mn[k]));

    // ---- tile-last epilogues (ordering via acq_rel atomics, no membar) ----
    if (tid == 0) {
        int f = 0;
        if (atom_add_acq_rel(&g_xctr[b * XT + xt], 1) == NC - 1) f |= 1;
        if (atom_add_acq_rel(&g_yctr[b * NC + c], 1) == XT - 1) f |= 2;
        sflags = f;
    }
    __syncthreads();
    int f = sflags;

    if (f) {
        float part = 0.0f;
        if (f & 1) {                       // x-tile complete: its 1024 points
            if (tid == 0) g_xctr[b * XT + xt] = 0;
            #pragma unroll
            for (int p = 0; p < NPAIR; p++) {
                int i0 = (2*p)   * THREADS + tid;
                int i1 = (2*p+1) * THREADS + tid;
                unsigned k0 = *((volatile unsigned*)&gx[i0]);
                unsigned k1 = *((volatile unsigned*)&gx[i1]);
                gx[i0] = 0u; gx[i1] = 0u;  // reset for next replay
                part += key_to_float(k0) + key_to_float(k1);
            }
        }
        if (f & 2) {                       // y-chunk complete: 64 full dists
            if (tid == 0) g_yctr[b * NC + c] = 0;
            if (tid < CH) {
                unsigned* gy = g_ykey + b * NPTS + c * CH + tid;
                unsigned k = *((volatile unsigned*)gy);
                *gy = 0u;                  // reset for next replay
                part += key_to_float(k);
            }
        }
        red[tid] = part;
        __syncthreads();
        #pragma unroll
        for (int st = THREADS / 2; st > 0; st >>= 1) {
            if (tid < st) red[tid] += red[tid + st];
            __syncthreads();
        }
        if (tid == 0)                      // deterministic fixed-point fold
            red_add_release(&g_total,
                (unsigned long long)((double)red[0] * 4294967296.0));
    }

    if (tid == 0) {
        if (atom_add_acq_rel(&g_done, 1) == NCTAS - 1) {
            unsigned long long tot = *((volatile unsigned long long*)&g_total);
            out[0] = (float)((double)tot * (1.0 / 4294967296.0)
                             / (double)(NPTS * BATCH));
            g_total = 0ull;                // reset for next replay
            g_done  = 0;
        }
    }
}

extern "C" void kernel_launch(void* const* d_in, const int* in_sizes, int n_in,
                              void* d_out, int out_size) {
    const float* x = (const float*)d_in[0];
    const float* y = (const float*)d_in[1];
    float* out = (float*)d_out;

    chamfer_fused<<<NCTAS, THREADS>>>(x, y, out);
}